// round 8
// baseline (speedup 1.0000x reference)
#include <cuda_runtime.h>
#include <cuda_fp16.h>
#include <math.h>
#include <stdint.h>

// Problem constants (B=8, H=W=64, C=512, nh=16, hd=32, ss=8)
#define M_TOT 32768
#define K_DIM 512
#define QKV_N 1536

// Scratch (allocation-free rule: __device__ globals)
__device__ __align__(16) __half g_qkvh[(size_t)M_TOT * QKV_N];  // q|k|v fp16
__device__ __align__(16) __half g_xh[(size_t)M_TOT * K_DIM];    // x fp16
__device__ __align__(16) __half g_ah[(size_t)M_TOT * K_DIM];    // attn-out fp16
__device__ __align__(16) __half g_wqh[(size_t)QKV_N * K_DIM];   // w_qkv fp16
__device__ __align__(16) __half g_wph[(size_t)K_DIM * K_DIM];   // w_proj fp16

// ---------------------------------------------------------------------------
// Helpers
// ---------------------------------------------------------------------------
__device__ __forceinline__ uint32_t smem_u32(const void* p) {
    uint32_t a;
    asm("{ .reg .u64 t; cvta.to.shared.u64 t, %1; cvt.u32.u64 %0, t; }" : "=r"(a) : "l"(p));
    return a;
}
__device__ __forceinline__ void cp16(uint32_t dst, const void* src) {
    asm volatile("cp.async.cg.shared.global [%0], [%1], 16;"
                 :: "r"(dst), "l"(__cvta_generic_to_global(src)));
}
__device__ __forceinline__ void cp_commit() { asm volatile("cp.async.commit_group;"); }
template <int Nwait>
__device__ __forceinline__ void cp_wait() {
    asm volatile("cp.async.wait_group %0;" :: "n"(Nwait));
}
__device__ __forceinline__ void ldm4(uint32_t (&r)[4], uint32_t addr) {
    asm volatile("ldmatrix.sync.aligned.m8n8.x4.shared.b16 {%0,%1,%2,%3}, [%4];"
                 : "=r"(r[0]), "=r"(r[1]), "=r"(r[2]), "=r"(r[3]) : "r"(addr));
}
__device__ __forceinline__ void mma_f16(float (&d)[4], const uint32_t (&a)[4],
                                        uint32_t b0, uint32_t b1) {
    asm volatile(
        "mma.sync.aligned.m16n8k16.row.col.f32.f16.f16.f32 "
        "{%0,%1,%2,%3}, {%4,%5,%6,%7}, {%8,%9}, {%0,%1,%2,%3};"
        : "+f"(d[0]), "+f"(d[1]), "+f"(d[2]), "+f"(d[3])
        : "r"(a[0]), "r"(a[1]), "r"(a[2]), "r"(a[3]), "r"(b0), "r"(b1));
}

// ---------------------------------------------------------------------------
// fp32 -> fp16 convert
// ---------------------------------------------------------------------------
__global__ void __launch_bounds__(256)
split_kernel(const float* __restrict__ src, __half* __restrict__ hi, int n4) {
    const int i = blockIdx.x * blockDim.x + threadIdx.x;
    if (i >= n4) return;
    const float4 f = ((const float4*)src)[i];
    ((__half2*)hi)[2 * i]     = __halves2half2(__float2half_rn(f.x), __float2half_rn(f.y));
    ((__half2*)hi)[2 * i + 1] = __halves2half2(__float2half_rn(f.z), __float2half_rn(f.w));
}

// ---------------------------------------------------------------------------
// fp16 tensor GEMM: C = A * B^T (+bias). BM=BN=128, BK=64, 8 warps
// (warp tile 64x32), 2-stage cp.async double buffer, compiler-scheduled
// ldmatrix/MMA body. Row stride 144B -> ldmatrix conflict-free (gcd(9,8)=1).
// ---------------------------------------------------------------------------
#define BK 64
#define RS_B 144                      // 128 data + 16 pad
#define TILE_BYTES (128 * RS_B)       // 18432
#define STAGE_BYTES (2 * TILE_BYTES)  // A | B
#define GEMM_SMEM (2 * STAGE_BYTES)   // 73728
#define NCH (K_DIM / BK)              // 8

template <int N, typename OutT, bool HAS_BIAS>
__device__ __forceinline__ void gemm_body(const __half* __restrict__ A_g,
                                          const __half* __restrict__ B_g,
                                          const float* __restrict__ bias,
                                          OutT* __restrict__ C) {
    extern __shared__ __align__(16) char smem[];
    const uint32_t sbase = smem_u32(smem);

    const int tid = threadIdx.x;
    const int warp = tid >> 5;
    const int lane = tid & 31;
    const int wm = warp & 1;
    const int wn = warp >> 1;
    const int g = lane >> 2;
    const int t = lane & 3;

    const int m0 = blockIdx.y * 128;
    const int n0 = blockIdx.x * 128;

    // cp.async: row = tid>>1 (0..127), 64-byte half-row hc = (tid&1)*32 halves
    const int crow = tid >> 1;
    const int hc = (tid & 1) * 32;
    const __half* a_src = A_g + (size_t)(m0 + crow) * K_DIM + hc;
    const __half* b_src = B_g + (size_t)(n0 + crow) * K_DIM + hc;
    const uint32_t cdst = sbase + crow * RS_B + (tid & 1) * 64;

    const uint32_t aRow = (uint32_t)(wm * 64 + (lane & 15)) * RS_B + ((lane >> 4) << 4);
    const uint32_t bRow = (uint32_t)(wn * 32 + (lane & 7) + ((lane >> 4) << 3)) * RS_B +
                          (((lane >> 3) & 1) << 4);

    float acc[4][4][4];
    #pragma unroll
    for (int i = 0; i < 4; i++)
        #pragma unroll
        for (int j = 0; j < 4; j++)
            #pragma unroll
            for (int r = 0; r < 4; r++) acc[i][j][r] = 0.f;

    auto issue = [&](int ch) {
        if (ch < NCH) {
            const int ko = ch * BK;
            const uint32_t d = cdst + (uint32_t)(ch & 1) * STAGE_BYTES;
            #pragma unroll
            for (int j = 0; j < 4; j++) {
                cp16(d + j * 16, a_src + ko + j * 8);
                cp16(d + TILE_BYTES + j * 16, b_src + ko + j * 8);
            }
        }
        cp_commit();
    };

    issue(0);

    for (int ch = 0; ch < NCH; ch++) {
        cp_wait<0>();
        __syncthreads();
        issue(ch + 1);

        const uint32_t sA = sbase + (uint32_t)(ch & 1) * STAGE_BYTES;
        const uint32_t sB = sA + TILE_BYTES;

        #pragma unroll
        for (int ks = 0; ks < 4; ks++) {
            uint32_t b0[4], b1[4];
            ldm4(b0, sB + bRow + ks * 32);
            ldm4(b1, sB + bRow + 16 * RS_B + ks * 32);
            #pragma unroll
            for (int mt = 0; mt < 4; mt++) {
                uint32_t a[4];
                ldm4(a, sA + aRow + mt * 16 * RS_B + ks * 32);
                mma_f16(acc[mt][0], a, b0[0], b0[1]);
                mma_f16(acc[mt][1], a, b0[2], b0[3]);
                mma_f16(acc[mt][2], a, b1[0], b1[1]);
                mma_f16(acc[mt][3], a, b1[2], b1[3]);
            }
        }
    }

    #pragma unroll
    for (int mt = 0; mt < 4; mt++) {
        #pragma unroll
        for (int nt = 0; nt < 4; nt++) {
            const int m = m0 + wm * 64 + mt * 16 + g;
            const int n = n0 + wn * 32 + nt * 8 + 2 * t;
            float2 r0 = make_float2(acc[mt][nt][0], acc[mt][nt][1]);
            float2 r1 = make_float2(acc[mt][nt][2], acc[mt][nt][3]);
            if (HAS_BIAS) {
                const float bz0 = bias[n], bz1 = bias[n + 1];
                r0.x += bz0; r0.y += bz1;
                r1.x += bz0; r1.y += bz1;
            }
            if (sizeof(OutT) == 2) {
                __half2* o0 = (__half2*)&C[(size_t)m * N + n];
                __half2* o1 = (__half2*)&C[(size_t)(m + 8) * N + n];
                *o0 = __halves2half2(__float2half_rn(r0.x), __float2half_rn(r0.y));
                *o1 = __halves2half2(__float2half_rn(r1.x), __float2half_rn(r1.y));
            } else {
                *(float2*)&((float*)C)[(size_t)m * N + n] = r0;
                *(float2*)&((float*)C)[(size_t)(m + 8) * N + n] = r1;
            }
        }
    }
}

__global__ void __launch_bounds__(256, 2)
qkv_gemm_kernel() {
    gemm_body<QKV_N, __half, false>(g_xh, g_wqh, nullptr, g_qkvh);
}

__global__ void __launch_bounds__(256, 2)
proj_gemm_kernel(const float* __restrict__ b_proj, float* __restrict__ out) {
    gemm_body<K_DIM, float, true>(g_ah, g_wph, b_proj, out);
}

// ---------------------------------------------------------------------------
// Fused stripe attention + LePE. Reads fp16 q/k/v, fp32 math, writes fp16.
// ---------------------------------------------------------------------------
__global__ void __launch_bounds__(256, 4)
attn_kernel(const float* __restrict__ lepe_h, const float* __restrict__ lepe_v) {
    __shared__ float qs[8][257];
    __shared__ float ks[8][257];
    __shared__ float vs[8][257];
    __shared__ float S[8][8][8];

    const int bidx = blockIdx.x;
    const int axis = bidx >> 12;
    const int rem  = bidx & 4095;
    const int b    = rem >> 9;
    const int r    = rem & 511;

    int tok_m[8];
    if (axis == 0) {
        const int s = r >> 6;
        const int w = r & 63;
        #pragma unroll
        for (int i = 0; i < 8; i++) tok_m[i] = (b << 12) + ((s * 8 + i) << 6) + w;
    } else {
        const int h = r >> 3;
        const int s = r & 7;
        #pragma unroll
        for (int i = 0; i < 8; i++) tok_m[i] = (b << 12) + (h << 6) + (s * 8 + i);
    }

    const int c_local = threadIdx.x;
    const int c = (axis << 8) + c_local;

    #pragma unroll
    for (int i = 0; i < 8; i++) {
        const __half* base = &g_qkvh[(size_t)tok_m[i] * QKV_N + c];
        qs[i][c_local] = __half2float(base[0]);
        ks[i][c_local] = __half2float(base[512]);
        vs[i][c_local] = __half2float(base[1024]);
    }
    __syncthreads();

    const float inv_scale = 0.17677669529663688f;  // 1/sqrt(32)
    #pragma unroll
    for (int e = 0; e < 2; e++) {
        const int idx = threadIdx.x + (e << 8);
        const int hh = idx >> 6;
        const int i = (idx >> 3) & 7;
        const int j = idx & 7;
        const int cbh = hh << 5;
        float sum = 0.f;
        #pragma unroll
        for (int d = 0; d < 32; d++) sum = fmaf(qs[i][cbh + d], ks[j][cbh + d], sum);
        S[hh][i][j] = sum * inv_scale;
    }
    __syncthreads();

    if (threadIdx.x < 64) {
        const int hh = threadIdx.x >> 3;
        const int i = threadIdx.x & 7;
        float* row = S[hh][i];
        float mx = row[0];
        #pragma unroll
        for (int j = 1; j < 8; j++) mx = fmaxf(mx, row[j]);
        float ex[8], sum = 0.f;
        #pragma unroll
        for (int j = 0; j < 8; j++) { ex[j] = __expf(row[j] - mx); sum += ex[j]; }
        const float inv = 1.f / sum;
        #pragma unroll
        for (int j = 0; j < 8; j++) row[j] = ex[j] * inv;
    }
    __syncthreads();

    const int head = c_local >> 5;
    const float* lw = (axis == 0) ? lepe_h : lepe_v;
    float wgt[9];
    #pragma unroll
    for (int tt = 0; tt < 9; tt++) wgt[tt] = lw[tt * 256 + c_local];

    #pragma unroll
    for (int i = 0; i < 8; i++) {
        float acc = 0.f;
        #pragma unroll
        for (int j = 0; j < 8; j++) acc = fmaf(S[head][i][j], vs[j][c_local], acc);

        const int m = tok_m[i];
        const int bb = m >> 12;
        const int h = (m >> 6) & 63;
        const int w = m & 63;
        float lep = 0.f;
        #pragma unroll
        for (int dh = -1; dh <= 1; dh++) {
            #pragma unroll
            for (int dw = -1; dw <= 1; dw++) {
                const int h2 = h + dh, w2 = w + dw;
                if (h2 >= 0 && h2 < 64 && w2 >= 0 && w2 < 64) {
                    const float vv = __half2float(
                        g_qkvh[(size_t)((bb << 12) + (h2 << 6) + w2) * QKV_N + 1024 + c]);
                    lep = fmaf(vv, wgt[(dh + 1) * 3 + (dw + 1)], lep);
                }
            }
        }
        g_ah[(size_t)m * K_DIM + c] = __float2half_rn(acc + lep);
    }
}

// ---------------------------------------------------------------------------
extern "C" void kernel_launch(void* const* d_in, const int* in_sizes, int n_in,
                              void* d_out, int out_size) {
    (void)in_sizes; (void)n_in; (void)out_size;
    const float* x      = (const float*)d_in[0];  // (8, 4096, 512)
    const float* w_qkv  = (const float*)d_in[1];  // (1536, 512)
    const float* w_proj = (const float*)d_in[2];  // (512, 512)
    const float* b_proj = (const float*)d_in[3];  // (512,)
    const float* lepe_h = (const float*)d_in[4];  // (3,3,1,256)
    const float* lepe_v = (const float*)d_in[5];  // (3,3,1,256)
    float* out = (float*)d_out;                   // (8, 4096, 512)

    static bool attr_set = false;
    if (!attr_set) {
        cudaFuncSetAttribute(qkv_gemm_kernel, cudaFuncAttributeMaxDynamicSharedMemorySize, GEMM_SMEM);
        cudaFuncSetAttribute(proj_gemm_kernel, cudaFuncAttributeMaxDynamicSharedMemorySize, GEMM_SMEM);
        attr_set = true;
    }

    __half* xh;  __half* wqh; __half* wph;
    cudaGetSymbolAddress((void**)&xh,  g_xh);
    cudaGetSymbolAddress((void**)&wqh, g_wqh);
    cudaGetSymbolAddress((void**)&wph, g_wph);

    dim3 blk(256);
    split_kernel<<<(M_TOT * K_DIM / 4 + 255) / 256, blk>>>(x, xh, M_TOT * K_DIM / 4);
    split_kernel<<<(QKV_N * K_DIM / 4 + 255) / 256, blk>>>(w_qkv, wqh, QKV_N * K_DIM / 4);
    split_kernel<<<(K_DIM * K_DIM / 4 + 255) / 256, blk>>>(w_proj, wph, K_DIM * K_DIM / 4);

    qkv_gemm_kernel<<<dim3(QKV_N / 128, M_TOT / 128), blk, GEMM_SMEM>>>();
    attn_kernel<<<8192, blk>>>(lepe_h, lepe_v);
    proj_gemm_kernel<<<dim3(K_DIM / 128, M_TOT / 128), blk, GEMM_SMEM>>>(b_proj, out);
}

// round 11
// speedup vs baseline: 1.0746x; 1.0746x over previous
#include <cuda_runtime.h>
#include <cuda_fp16.h>
#include <math.h>
#include <stdint.h>

// Problem constants (B=8, H=W=64, C=512, nh=16, hd=32, ss=8)
#define M_TOT 32768
#define K_DIM 512
#define QKV_N 1536

// Scratch (allocation-free rule: __device__ globals)
__device__ __align__(16) __half g_qkvh[(size_t)M_TOT * QKV_N];  // q|k|v fp16
__device__ __align__(16) __half g_xh[(size_t)M_TOT * K_DIM];    // x fp16
__device__ __align__(16) __half g_ah[(size_t)M_TOT * K_DIM];    // attn-out fp16
__device__ __align__(16) __half g_wqh[(size_t)QKV_N * K_DIM];   // w_qkv fp16
__device__ __align__(16) __half g_wph[(size_t)K_DIM * K_DIM];   // w_proj fp16

// ---------------------------------------------------------------------------
// Helpers
// ---------------------------------------------------------------------------
__device__ __forceinline__ uint32_t smem_u32(const void* p) {
    uint32_t a;
    asm("{ .reg .u64 t; cvta.to.shared.u64 t, %1; cvt.u32.u64 %0, t; }" : "=r"(a) : "l"(p));
    return a;
}
__device__ __forceinline__ void cp16(uint32_t dst, const void* src) {
    asm volatile("cp.async.cg.shared.global [%0], [%1], 16;"
                 :: "r"(dst), "l"(__cvta_generic_to_global(src)));
}
__device__ __forceinline__ void cp_commit() { asm volatile("cp.async.commit_group;"); }
template <int Nwait>
__device__ __forceinline__ void cp_wait() {
    asm volatile("cp.async.wait_group %0;" :: "n"(Nwait));
}
__device__ __forceinline__ void ldm4(uint32_t (&r)[4], uint32_t addr) {
    asm volatile("ldmatrix.sync.aligned.m8n8.x4.shared.b16 {%0,%1,%2,%3}, [%4];"
                 : "=r"(r[0]), "=r"(r[1]), "=r"(r[2]), "=r"(r[3]) : "r"(addr));
}
__device__ __forceinline__ void mma_f16(float (&d)[4], const uint32_t (&a)[4],
                                        uint32_t b0, uint32_t b1) {
    asm volatile(
        "mma.sync.aligned.m16n8k16.row.col.f32.f16.f16.f32 "
        "{%0,%1,%2,%3}, {%4,%5,%6,%7}, {%8,%9}, {%0,%1,%2,%3};"
        : "+f"(d[0]), "+f"(d[1]), "+f"(d[2]), "+f"(d[3])
        : "r"(a[0]), "r"(a[1]), "r"(a[2]), "r"(a[3]), "r"(b0), "r"(b1));
}

// ---------------------------------------------------------------------------
// fp32 -> fp16 convert (one tensor per launch; R8-proven path)
// ---------------------------------------------------------------------------
__global__ void __launch_bounds__(256)
split_kernel(const float* __restrict__ src, __half* __restrict__ hi, int n4) {
    const int i = blockIdx.x * blockDim.x + threadIdx.x;
    if (i >= n4) return;
    const float4 f = ((const float4*)src)[i];
    ((__half2*)hi)[2 * i]     = __halves2half2(__float2half_rn(f.x), __float2half_rn(f.y));
    ((__half2*)hi)[2 * i + 1] = __halves2half2(__float2half_rn(f.z), __float2half_rn(f.w));
}

// ---------------------------------------------------------------------------
// fp16 tensor GEMM (R6-verified config): C = A * B^T (+bias).
// BM=BN=128, BK=32, 8 warps (warp tile 64x32), 4-stage cp.async
// (wait_group 2), plain compiler-scheduled ldmatrix/MMA body.
// Row stride 80B -> ldmatrix conflict-free.
// ---------------------------------------------------------------------------
#define BK 32
#define RS_B 80
#define TILE_BYTES (128 * RS_B)       // 10240
#define STAGE_BYTES (2 * TILE_BYTES)  // A | B
#define NSTAGE 4
#define GEMM_SMEM (NSTAGE * STAGE_BYTES)  // 81920
#define NCH (K_DIM / BK)              // 16

template <int N, typename OutT, bool HAS_BIAS>
__device__ __forceinline__ void gemm_body(const __half* __restrict__ A_g,
                                          const __half* __restrict__ B_g,
                                          const float* __restrict__ bias,
                                          OutT* __restrict__ C) {
    extern __shared__ __align__(16) char smem[];
    const uint32_t sbase = smem_u32(smem);

    const int tid = threadIdx.x;
    const int warp = tid >> 5;
    const int lane = tid & 31;
    const int wm = warp & 1;
    const int wn = warp >> 1;
    const int g = lane >> 2;
    const int t = lane & 3;

    const int m0 = blockIdx.y * 128;
    const int n0 = blockIdx.x * 128;

    const int crow = tid >> 1;
    const int cc = (tid & 1) * 2;
    const __half* a_src = A_g + (size_t)(m0 + crow) * K_DIM + cc * 8;
    const __half* b_src = B_g + (size_t)(n0 + crow) * K_DIM + cc * 8;
    const uint32_t cdst = sbase + crow * RS_B + cc * 16;

    const uint32_t aRow = (uint32_t)(wm * 64 + (lane & 15)) * RS_B + ((lane >> 4) << 4);
    const uint32_t bRow = (uint32_t)(wn * 32 + (lane & 7) + ((lane >> 4) << 3)) * RS_B +
                          (((lane >> 3) & 1) << 4);

    float acc[4][4][4];
    #pragma unroll
    for (int i = 0; i < 4; i++)
        #pragma unroll
        for (int j = 0; j < 4; j++)
            #pragma unroll
            for (int r = 0; r < 4; r++) acc[i][j][r] = 0.f;

    auto issue = [&](int ch) {
        if (ch < NCH) {
            const int ko = ch * BK;
            const uint32_t d = cdst + (uint32_t)(ch % NSTAGE) * STAGE_BYTES;
            cp16(d, a_src + ko);              cp16(d + 16, a_src + ko + 8);
            cp16(d + TILE_BYTES, b_src + ko); cp16(d + TILE_BYTES + 16, b_src + ko + 8);
        }
        cp_commit();
    };

    #pragma unroll
    for (int s = 0; s < NSTAGE - 1; s++) issue(s);

    for (int ch = 0; ch < NCH; ch++) {
        cp_wait<NSTAGE - 2>();
        __syncthreads();
        issue(ch + NSTAGE - 1);

        const uint32_t sA = sbase + (uint32_t)(ch % NSTAGE) * STAGE_BYTES;
        const uint32_t sB = sA + TILE_BYTES;

        #pragma unroll
        for (int ks = 0; ks < 2; ks++) {
            uint32_t b0[4], b1[4];
            ldm4(b0, sB + bRow + ks * 32);
            ldm4(b1, sB + bRow + 16 * RS_B + ks * 32);
            #pragma unroll
            for (int mt = 0; mt < 4; mt++) {
                uint32_t a[4];
                ldm4(a, sA + aRow + mt * 16 * RS_B + ks * 32);
                mma_f16(acc[mt][0], a, b0[0], b0[1]);
                mma_f16(acc[mt][1], a, b0[2], b0[3]);
                mma_f16(acc[mt][2], a, b1[0], b1[1]);
                mma_f16(acc[mt][3], a, b1[2], b1[3]);
            }
        }
    }

    #pragma unroll
    for (int mt = 0; mt < 4; mt++) {
        #pragma unroll
        for (int nt = 0; nt < 4; nt++) {
            const int m = m0 + wm * 64 + mt * 16 + g;
            const int n = n0 + wn * 32 + nt * 8 + 2 * t;
            float2 r0 = make_float2(acc[mt][nt][0], acc[mt][nt][1]);
            float2 r1 = make_float2(acc[mt][nt][2], acc[mt][nt][3]);
            if (HAS_BIAS) {
                const float bz0 = bias[n], bz1 = bias[n + 1];
                r0.x += bz0; r0.y += bz1;
                r1.x += bz0; r1.y += bz1;
            }
            if (sizeof(OutT) == 2) {
                *(__half2*)&C[(size_t)m * N + n] =
                    __halves2half2(__float2half_rn(r0.x), __float2half_rn(r0.y));
                *(__half2*)&C[(size_t)(m + 8) * N + n] =
                    __halves2half2(__float2half_rn(r1.x), __float2half_rn(r1.y));
            } else {
                *(float2*)&((float*)C)[(size_t)m * N + n] = r0;
                *(float2*)&((float*)C)[(size_t)(m + 8) * N + n] = r1;
            }
        }
    }
}

__global__ void __launch_bounds__(256, 2)
qkv_gemm_kernel() {
    gemm_body<QKV_N, __half, false>(g_xh, g_wqh, nullptr, g_qkvh);
}

__global__ void __launch_bounds__(256, 2)
proj_gemm_kernel(const float* __restrict__ b_proj, float* __restrict__ out) {
    gemm_body<K_DIM, float, true>(g_ah, g_wph, b_proj, out);
}

// ---------------------------------------------------------------------------
// Fused stripe attention + LePE. fp16 in, fp32 math, fp16 out.
// ---------------------------------------------------------------------------
__global__ void __launch_bounds__(256, 4)
attn_kernel(const float* __restrict__ lepe_h, const float* __restrict__ lepe_v) {
    __shared__ float qs[8][257];
    __shared__ float ks[8][257];
    __shared__ float vs[8][257];
    __shared__ float S[8][8][8];

    const int bidx = blockIdx.x;
    const int axis = bidx >> 12;
    const int rem  = bidx & 4095;
    const int b    = rem >> 9;
    const int r    = rem & 511;

    int tok_m[8];
    if (axis == 0) {
        const int s = r >> 6;
        const int w = r & 63;
        #pragma unroll
        for (int i = 0; i < 8; i++) tok_m[i] = (b << 12) + ((s * 8 + i) << 6) + w;
    } else {
        const int h = r >> 3;
        const int s = r & 7;
        #pragma unroll
        for (int i = 0; i < 8; i++) tok_m[i] = (b << 12) + (h << 6) + (s * 8 + i);
    }

    const int c_local = threadIdx.x;
    const int c = (axis << 8) + c_local;

    #pragma unroll
    for (int i = 0; i < 8; i++) {
        const __half* base = &g_qkvh[(size_t)tok_m[i] * QKV_N + c];
        qs[i][c_local] = __half2float(base[0]);
        ks[i][c_local] = __half2float(base[512]);
        vs[i][c_local] = __half2float(base[1024]);
    }
    __syncthreads();

    const float inv_scale = 0.17677669529663688f;  // 1/sqrt(32)
    #pragma unroll
    for (int e = 0; e < 2; e++) {
        const int idx = threadIdx.x + (e << 8);
        const int hh = idx >> 6;
        const int i = (idx >> 3) & 7;
        const int j = idx & 7;
        const int cbh = hh << 5;
        float sum = 0.f;
        #pragma unroll
        for (int d = 0; d < 32; d++) sum = fmaf(qs[i][cbh + d], ks[j][cbh + d], sum);
        S[hh][i][j] = sum * inv_scale;
    }
    __syncthreads();

    if (threadIdx.x < 64) {
        const int hh = threadIdx.x >> 3;
        const int i = threadIdx.x & 7;
        float* row = S[hh][i];
        float mx = row[0];
        #pragma unroll
        for (int j = 1; j < 8; j++) mx = fmaxf(mx, row[j]);
        float ex[8], sum = 0.f;
        #pragma unroll
        for (int j = 0; j < 8; j++) { ex[j] = __expf(row[j] - mx); sum += ex[j]; }
        const float inv = 1.f / sum;
        #pragma unroll
        for (int j = 0; j < 8; j++) row[j] = ex[j] * inv;
    }
    __syncthreads();

    const int head = c_local >> 5;
    const float* lw = (axis == 0) ? lepe_h : lepe_v;
    float wgt[9];
    #pragma unroll
    for (int tt = 0; tt < 9; tt++) wgt[tt] = lw[tt * 256 + c_local];

    #pragma unroll
    for (int i = 0; i < 8; i++) {
        float acc = 0.f;
        #pragma unroll
        for (int j = 0; j < 8; j++) acc = fmaf(S[head][i][j], vs[j][c_local], acc);

        const int m = tok_m[i];
        const int bb = m >> 12;
        const int h = (m >> 6) & 63;
        const int w = m & 63;
        float lep = 0.f;
        #pragma unroll
        for (int dh = -1; dh <= 1; dh++) {
            #pragma unroll
            for (int dw = -1; dw <= 1; dw++) {
                const int h2 = h + dh, w2 = w + dw;
                if (h2 >= 0 && h2 < 64 && w2 >= 0 && w2 < 64) {
                    const float vv = __half2float(
                        g_qkvh[(size_t)((bb << 12) + (h2 << 6) + w2) * QKV_N + 1024 + c]);
                    lep = fmaf(vv, wgt[(dh + 1) * 3 + (dw + 1)], lep);
                }
            }
        }
        g_ah[(size_t)m * K_DIM + c] = __float2half_rn(acc + lep);
    }
}

// ---------------------------------------------------------------------------
extern "C" void kernel_launch(void* const* d_in, const int* in_sizes, int n_in,
                              void* d_out, int out_size) {
    (void)in_sizes; (void)n_in; (void)out_size;
    const float* x      = (const float*)d_in[0];  // (8, 4096, 512)
    const float* w_qkv  = (const float*)d_in[1];  // (1536, 512)
    const float* w_proj = (const float*)d_in[2];  // (512, 512)
    const float* b_proj = (const float*)d_in[3];  // (512,)
    const float* lepe_h = (const float*)d_in[4];  // (3,3,1,256)
    const float* lepe_v = (const float*)d_in[5];  // (3,3,1,256)
    float* out = (float*)d_out;                   // (8, 4096, 512)

    static bool attr_set = false;
    if (!attr_set) {
        cudaFuncSetAttribute(qkv_gemm_kernel, cudaFuncAttributeMaxDynamicSharedMemorySize, GEMM_SMEM);
        cudaFuncSetAttribute(proj_gemm_kernel, cudaFuncAttributeMaxDynamicSharedMemorySize, GEMM_SMEM);
        attr_set = true;
    }

    __half* xh;  __half* wqh; __half* wph;
    cudaGetSymbolAddress((void**)&xh,  g_xh);
    cudaGetSymbolAddress((void**)&wqh, g_wqh);
    cudaGetSymbolAddress((void**)&wph, g_wph);

    dim3 blk(256);
    split_kernel<<<(M_TOT * K_DIM / 4 + 255) / 256, blk>>>(x, xh, M_TOT * K_DIM / 4);
    split_kernel<<<(QKV_N * K_DIM / 4 + 255) / 256, blk>>>(w_qkv, wqh, QKV_N * K_DIM / 4);
    split_kernel<<<(K_DIM * K_DIM / 4 + 255) / 256, blk>>>(w_proj, wph, K_DIM * K_DIM / 4);

    qkv_gemm_kernel<<<dim3(QKV_N / 128, M_TOT / 128), blk, GEMM_SMEM>>>();
    attn_kernel<<<8192, blk>>>(lepe_h, lepe_v);
    proj_gemm_kernel<<<dim3(K_DIM / 128, M_TOT / 128), blk, GEMM_SMEM>>>(b_proj, out);
}